// round 1
// baseline (speedup 1.0000x reference)
#include <cuda_runtime.h>
#include <cstdint>

#define Bn 4
#define Ln 8192
#define Hn 128
#define Pn 64

typedef unsigned long long ull;

// Scratch (allocation-free rule: __device__ globals)
__device__ __align__(16) float  g_Bu[Bn * Pn * 2 * Ln];   // [b][p][c][L]
__device__ __align__(16) float2 g_ys[Bn * Pn * Ln];        // [b][p][L] (re,im)

// ---------- packed f32x2 helpers ----------
__device__ __forceinline__ ull dup2(float v) {
    ull r; unsigned uv = __float_as_uint(v);
    asm("mov.b64 %0, {%1, %1};" : "=l"(r) : "r"(uv));
    return r;
}
__device__ __forceinline__ ull fma2(ull a, ull b, ull c) {
    ull d;
    asm("fma.rn.f32x2 %0, %1, %2, %3;" : "=l"(d) : "l"(a), "l"(b), "l"(c));
    return d;
}
__device__ __forceinline__ void unpack2(ull v, float &lo, float &hi) {
    unsigned a, b;
    asm("mov.b64 {%0, %1}, %2;" : "=r"(a), "=r"(b) : "l"(v));
    lo = __uint_as_float(a); hi = __uint_as_float(b);
}

// ---------- Kernel 1: Bu[l,p,c] = sum_h u[l,h] * B_c[p,h] ----------
#define UP 132   // u smem pitch (transposed [h][l])
#define BP 258   // B smem pitch ([p][2h+c] interleaved pairs)

__global__ __launch_bounds__(256) void k_gemmB(const float* __restrict__ u,
                                               const float* __restrict__ Br,
                                               const float* __restrict__ Bi) {
    extern __shared__ float sm[];
    float* su = sm;                // [128 h][UP]  su[h*UP + l]
    float* sb = sm + 128 * UP;     // [64 p][BP]   sb[p*BP + 2h + c]
    const int b = blockIdx.y, lt = blockIdx.x;   // Ltile = 128
    const int tid = threadIdx.x;

    const float* ug = u + ((size_t)b * Ln + (size_t)lt * 128) * Hn;
    for (int e = tid; e < 128 * Hn; e += 256) {
        int l = e >> 7, h = e & 127;
        su[h * UP + l] = ug[e];
    }
    for (int e = tid; e < Pn * Hn; e += 256) {
        int p = e >> 7, h = e & 127;
        sb[p * BP + 2 * h]     = Br[e];
        sb[p * BP + 2 * h + 1] = Bi[e];
    }
    __syncthreads();

    const int tx = tid & 15, ty = tid >> 4;
    const int l0 = tx * 8, p0 = ty * 4;

    ull acc[8][4];
#pragma unroll
    for (int i = 0; i < 8; ++i)
#pragma unroll
        for (int j = 0; j < 4; ++j) acc[i][j] = 0ull;

#pragma unroll 2
    for (int h = 0; h < Hn; ++h) {
        float4 ua = *(const float4*)&su[h * UP + l0];
        float4 ub = *(const float4*)&su[h * UP + l0 + 4];
        ull up[8];
        up[0] = dup2(ua.x); up[1] = dup2(ua.y); up[2] = dup2(ua.z); up[3] = dup2(ua.w);
        up[4] = dup2(ub.x); up[5] = dup2(ub.y); up[6] = dup2(ub.z); up[7] = dup2(ub.w);
#pragma unroll
        for (int j = 0; j < 4; ++j) {
            ull bp = *(const ull*)&sb[(p0 + j) * BP + 2 * h];
#pragma unroll
            for (int i = 0; i < 8; ++i) acc[i][j] = fma2(up[i], bp, acc[i][j]);
        }
    }

#pragma unroll
    for (int j = 0; j < 4; ++j) {
        int p = p0 + j;
        float re[8], im[8];
#pragma unroll
        for (int i = 0; i < 8; ++i) unpack2(acc[i][j], re[i], im[i]);
        size_t base = ((size_t)(b * Pn + p) * 2) * Ln + (size_t)lt * 128 + l0;
        *(float4*)&g_Bu[base]          = make_float4(re[0], re[1], re[2], re[3]);
        *(float4*)&g_Bu[base + 4]      = make_float4(re[4], re[5], re[6], re[7]);
        *(float4*)&g_Bu[base + Ln]     = make_float4(im[0], im[1], im[2], im[3]);
        *(float4*)&g_Bu[base + Ln + 4] = make_float4(im[4], im[5], im[6], im[7]);
    }
}

// ---------- Kernel 2: chunked linear-recurrence scan ----------
// state (z,x): z' = m11 z + m12 x + c1*Bu ;  x' = m21 z + m22 x + c2*Bu
// one block per (b,p); both complex comps in a 4-float state.
__global__ __launch_bounds__(256) void k_recur(const float* __restrict__ A_diag,
                                               const float* __restrict__ steps) {
    const int p = blockIdx.x, b = blockIdx.y;
    const int t = threadIdx.x;

    float a  = fmaxf(A_diag[p], 0.f);
    float s  = 1.f / (1.f + expf(-steps[p]));
    float s2a   = s * s * a;
    float schur = 1.f / (1.f + s2a);
    float m11 = 1.f - s2a * schur;
    float m12 = -s * a * schur;
    float m21 = s * schur;
    float m22 = schur;
    float c1 = m11 * s, c2 = m21 * s;

    const size_t chain = (size_t)(b * Pn + p);
    const float4* bre = (const float4*)(g_Bu + (chain * 2 + 0) * Ln + t * 32);
    const float4* bim = (const float4*)(g_Bu + (chain * 2 + 1) * Ln + t * 32);

    float fre[32], fim[32];
#pragma unroll
    for (int k = 0; k < 8; ++k) {
        float4 v = bre[k];
        fre[4*k] = v.x; fre[4*k+1] = v.y; fre[4*k+2] = v.z; fre[4*k+3] = v.w;
        float4 w = bim[k];
        fim[4*k] = w.x; fim[4*k+1] = w.y; fim[4*k+2] = w.z; fim[4*k+3] = w.w;
    }

    // local pass from zero state
    float zr = 0.f, xr = 0.f, zi = 0.f, xi = 0.f;
#pragma unroll
    for (int i = 0; i < 32; ++i) {
        float nzr = fmaf(m11, zr, fmaf(m12, xr, c1 * fre[i]));
        float nxr = fmaf(m21, zr, fmaf(m22, xr, c2 * fre[i]));
        float nzi = fmaf(m11, zi, fmaf(m12, xi, c1 * fim[i]));
        float nxi = fmaf(m21, zi, fmaf(m22, xi, c2 * fim[i]));
        zr = nzr; xr = nxr; zi = nzi; xi = nxi;
    }

    // M^32 by repeated squaring
    float q00 = m11, q01 = m12, q10 = m21, q11 = m22;
#pragma unroll
    for (int k = 0; k < 5; ++k) {
        float n00 = q00*q00 + q01*q10, n01 = q00*q01 + q01*q11;
        float n10 = q10*q00 + q11*q10, n11 = q10*q01 + q11*q11;
        q00 = n00; q01 = n01; q10 = n10; q11 = n11;
    }

    // Hillis-Steele inclusive scan over segment offsets (affine b-parts)
    __shared__ float4 sv[256];
    float4 v = make_float4(zr, xr, zi, xi);
    int off = 1;
#pragma unroll
    for (int st = 0; st < 8; ++st) {
        sv[t] = v;
        __syncthreads();
        if (t >= off) {
            float4 w = sv[t - off];
            v.x += q00 * w.x + q01 * w.y;
            v.y += q10 * w.x + q11 * w.y;
            v.z += q00 * w.z + q01 * w.w;
            v.w += q10 * w.z + q11 * w.w;
        }
        __syncthreads();
        float n00 = q00*q00 + q01*q10, n01 = q00*q01 + q01*q11;
        float n10 = q10*q00 + q11*q10, n11 = q10*q01 + q11*q11;
        q00 = n00; q01 = n01; q10 = n10; q11 = n11;
        off <<= 1;
    }
    sv[t] = v;
    __syncthreads();
    float4 s0 = make_float4(0.f, 0.f, 0.f, 0.f);
    if (t > 0) s0 = sv[t - 1];

    // replay with correct start state, emit x (position) component
    zr = s0.x; xr = s0.y; zi = s0.z; xi = s0.w;
    float2* ys = g_ys + chain * Ln + t * 32;
#pragma unroll
    for (int i = 0; i < 32; ++i) {
        float nzr = fmaf(m11, zr, fmaf(m12, xr, c1 * fre[i]));
        float nxr = fmaf(m21, zr, fmaf(m22, xr, c2 * fre[i]));
        float nzi = fmaf(m11, zi, fmaf(m12, xi, c1 * fim[i]));
        float nxi = fmaf(m21, zi, fmaf(m22, xi, c2 * fim[i]));
        zr = nzr; xr = nxr; zi = nzi; xi = nxi;
        ys[i] = make_float2(xr, xi);
    }
}

// ---------- Kernel 3: y = ys_re @ Cr^T - ys_im @ Ci^T + D*u ----------
#define YP 132   // ys smem pitch: [p][2l+c]
#define CP 130   // C  smem pitch: [h][2p+c] holding (Cr, -Ci)

__global__ __launch_bounds__(256) void k_gemmD(const float* __restrict__ u,
                                               const float* __restrict__ Cr,
                                               const float* __restrict__ Ci,
                                               const float* __restrict__ Dv,
                                               float* __restrict__ out) {
    extern __shared__ float sm[];
    float* sy = sm;             // [64 p][YP]
    float* sC = sm + Pn * YP;   // [128 h][CP]
    const int b = blockIdx.y, lt = blockIdx.x;   // Ltile = 64
    const int tid = threadIdx.x;

    for (int e = tid; e < Pn * 64; e += 256) {
        int p = e >> 6, l = e & 63;
        float2 v = g_ys[(size_t)(b * Pn + p) * Ln + (size_t)lt * 64 + l];
        sy[p * YP + 2 * l]     = v.x;
        sy[p * YP + 2 * l + 1] = v.y;
    }
    for (int e = tid; e < Hn * Pn; e += 256) {
        int h = e >> 6, p = e & 63;
        sC[h * CP + 2 * p]     = Cr[e];
        sC[h * CP + 2 * p + 1] = -Ci[e];
    }
    __syncthreads();

    const int tx = tid & 15, ty = tid >> 4;
    const int l0 = 4 * tx, h0 = 8 * ty;

    ull acc[4][8];
#pragma unroll
    for (int i = 0; i < 4; ++i)
#pragma unroll
        for (int j = 0; j < 8; ++j) acc[i][j] = 0ull;

    const ull* syp = (const ull*)sy;   // pitch YP/2 = 66 pairs
    const ull* sCp = (const ull*)sC;   // pitch CP/2 = 65 pairs

#pragma unroll 2
    for (int p = 0; p < Pn; ++p) {
        ull yp[4];
#pragma unroll
        for (int i = 0; i < 4; ++i) yp[i] = syp[p * (YP / 2) + l0 + i];
#pragma unroll
        for (int j = 0; j < 8; ++j) {
            ull cp = sCp[(h0 + j) * (CP / 2) + p];
#pragma unroll
            for (int i = 0; i < 4; ++i) acc[i][j] = fma2(yp[i], cp, acc[i][j]);
        }
    }

    float4 d0 = *(const float4*)&Dv[h0];
    float4 d1 = *(const float4*)&Dv[h0 + 4];
    float dv[8] = {d0.x, d0.y, d0.z, d0.w, d1.x, d1.y, d1.z, d1.w};

#pragma unroll
    for (int i = 0; i < 4; ++i) {
        size_t row = ((size_t)b * Ln + (size_t)lt * 64 + l0 + i) * Hn + h0;
        float4 u0 = *(const float4*)&u[row];
        float4 u1 = *(const float4*)&u[row + 4];
        float uu[8] = {u0.x, u0.y, u0.z, u0.w, u1.x, u1.y, u1.z, u1.w};
        float y[8];
#pragma unroll
        for (int j = 0; j < 8; ++j) {
            float lo, hi; unpack2(acc[i][j], lo, hi);
            y[j] = lo + hi + dv[j] * uu[j];
        }
        *(float4*)&out[row]     = make_float4(y[0], y[1], y[2], y[3]);
        *(float4*)&out[row + 4] = make_float4(y[4], y[5], y[6], y[7]);
    }
}

// ---------- launch ----------
extern "C" void kernel_launch(void* const* d_in, const int* in_sizes, int n_in,
                              void* d_out, int out_size) {
    const float* u     = (const float*)d_in[0];
    const float* A_d   = (const float*)d_in[1];
    const float* Br    = (const float*)d_in[2];
    const float* Bi    = (const float*)d_in[3];
    const float* Cr    = (const float*)d_in[4];
    const float* Ci    = (const float*)d_in[5];
    const float* Dv    = (const float*)d_in[6];
    const float* steps = (const float*)d_in[7];
    float* out = (float*)d_out;

    const int SMB = (128 * UP + Pn * BP) * 4;   // ~130.5 KB
    const int SMD = (Pn * YP + Hn * CP) * 4;    // ~98 KB
    cudaFuncSetAttribute(k_gemmB, cudaFuncAttributeMaxDynamicSharedMemorySize, SMB);
    cudaFuncSetAttribute(k_gemmD, cudaFuncAttributeMaxDynamicSharedMemorySize, SMD);

    k_gemmB<<<dim3(Ln / 128, Bn), 256, SMB>>>(u, Br, Bi);
    k_recur<<<dim3(Pn, Bn), 256>>>(A_d, steps);
    k_gemmD<<<dim3(Ln / 64, Bn), 256, SMD>>>(u, Cr, Ci, Dv, out);
}

// round 2
// speedup vs baseline: 1.0883x; 1.0883x over previous
#include <cuda_runtime.h>
#include <cstdint>

#define Bn 4
#define Ln 8192
#define Hn 128
#define Pn 64

typedef unsigned long long ull;

// Scratch: interleaved (re,im) pairs
__device__ __align__(16) float g_Bu[Bn * Pn * Ln * 2];   // [b][p][l][2]
__device__ __align__(16) float g_ys[Bn * Pn * Ln * 2];   // [b][p][l][2]

// ---------- packed f32x2 helpers ----------
__device__ __forceinline__ ull dup2(float v) {
    ull r; unsigned uv = __float_as_uint(v);
    asm("mov.b64 %0, {%1, %1};" : "=l"(r) : "r"(uv));
    return r;
}
__device__ __forceinline__ ull fma2(ull a, ull b, ull c) {
    ull d;
    asm("fma.rn.f32x2 %0, %1, %2, %3;" : "=l"(d) : "l"(a), "l"(b), "l"(c));
    return d;
}
__device__ __forceinline__ ull mul2(ull a, ull b) {
    ull d;
    asm("mul.rn.f32x2 %0, %1, %2;" : "=l"(d) : "l"(a), "l"(b));
    return d;
}
__device__ __forceinline__ void unpack2(ull v, float &lo, float &hi) {
    unsigned a, b;
    asm("mov.b64 {%0, %1}, %2;" : "=r"(a), "=r"(b) : "l"(v));
    lo = __uint_as_float(a); hi = __uint_as_float(b);
}

// ---------- Kernel 1: Bu[b][p][l][c] = sum_h u[l,h] * B_c[p,h] ----------
#define UP 68    // u smem pitch: [128 h][64 l + pad]
#define BPW 260  // B smem pitch (floats): [64 p][2h interleaved + pad]

__global__ __launch_bounds__(256) void k_gemmB(const float* __restrict__ u,
                                               const float* __restrict__ Br,
                                               const float* __restrict__ Bi) {
    extern __shared__ float sm[];
    float* su = sm;                 // [128][UP]
    float* sb = sm + 128 * UP;      // [64][BPW]
    const int b = blockIdx.y, lt = blockIdx.x;   // Ltile = 64
    const int tid = threadIdx.x;

    const float* ug = u + ((size_t)b * Ln + (size_t)lt * 64) * Hn;
    for (int e = tid; e < 64 * Hn; e += 256) {
        int l = e >> 7, h = e & 127;
        su[h * UP + l] = ug[e];
    }
    for (int e = tid; e < Pn * Hn; e += 256) {
        int p = e >> 7, h = e & 127;
        sb[p * BPW + 2 * h]     = Br[e];
        sb[p * BPW + 2 * h + 1] = Bi[e];
    }
    __syncthreads();

    const int tx = tid & 7, ty = tid >> 3;      // ty 0..31
    const int lA = tx * 4, lB = 32 + tx * 4;
    const int p0 = ty * 2;

    ull accA[4][2], accB[4][2];
#pragma unroll
    for (int i = 0; i < 4; ++i) { accA[i][0]=0; accA[i][1]=0; accB[i][0]=0; accB[i][1]=0; }

    const float* suA = su + lA;
    const float* suB = su + lB;

#pragma unroll 2
    for (int h = 0; h < Hn; h += 2) {
        float4 a0 = *(const float4*)(suA + h * UP);
        float4 a1 = *(const float4*)(suA + (h + 1) * UP);
        float4 c0 = *(const float4*)(suB + h * UP);
        float4 c1 = *(const float4*)(suB + (h + 1) * UP);
        ull dA0[4] = {dup2(a0.x), dup2(a0.y), dup2(a0.z), dup2(a0.w)};
        ull dA1[4] = {dup2(a1.x), dup2(a1.y), dup2(a1.z), dup2(a1.w)};
        ull dB0[4] = {dup2(c0.x), dup2(c0.y), dup2(c0.z), dup2(c0.w)};
        ull dB1[4] = {dup2(c1.x), dup2(c1.y), dup2(c1.z), dup2(c1.w)};
#pragma unroll
        for (int j = 0; j < 2; ++j) {
            ulonglong2 bb = *(const ulonglong2*)(sb + (p0 + j) * BPW + 2 * h);
#pragma unroll
            for (int i = 0; i < 4; ++i) {
                accA[i][j] = fma2(dA0[i], bb.x, accA[i][j]);
                accA[i][j] = fma2(dA1[i], bb.y, accA[i][j]);
                accB[i][j] = fma2(dB0[i], bb.x, accB[i][j]);
                accB[i][j] = fma2(dB1[i], bb.y, accB[i][j]);
            }
        }
    }

#pragma unroll
    for (int j = 0; j < 2; ++j) {
        int p = p0 + j;
        size_t base = ((size_t)(b * Pn + p) * Ln + (size_t)lt * 64) * 2;
        ulonglong2 s0 = {accA[0][j], accA[1][j]};
        ulonglong2 s1 = {accA[2][j], accA[3][j]};
        ulonglong2 s2 = {accB[0][j], accB[1][j]};
        ulonglong2 s3 = {accB[2][j], accB[3][j]};
        *(ulonglong2*)&g_Bu[base + 2 * lA]     = s0;
        *(ulonglong2*)&g_Bu[base + 2 * lA + 4] = s1;
        *(ulonglong2*)&g_Bu[base + 2 * lB]     = s2;
        *(ulonglong2*)&g_Bu[base + 2 * lB + 4] = s3;
    }
}

// ---------- Kernel 2: chunked linear-recurrence scan (f32x2 packed re/im) ----------
__global__ __launch_bounds__(512) void k_recur(const float* __restrict__ A_diag,
                                               const float* __restrict__ steps) {
    const int p = blockIdx.x, b = blockIdx.y;
    const int t = threadIdx.x;

    float a  = fmaxf(A_diag[p], 0.f);
    float s  = 1.f / (1.f + expf(-steps[p]));
    float s2a   = s * s * a;
    float schur = 1.f / (1.f + s2a);
    float m11 = 1.f - s2a * schur;
    float m12 = -s * a * schur;
    float m21 = s * schur;
    float m22 = schur;
    ull M11 = dup2(m11), M12 = dup2(m12), M21 = dup2(m21), M22 = dup2(m22);
    ull C1 = dup2(m11 * s), C2 = dup2(m21 * s);

    const size_t chain = (size_t)(b * Pn + p);
    const ulonglong2* src = (const ulonglong2*)(g_Bu) + chain * (Ln / 2) + t * 8;

    ull f[16];
#pragma unroll
    for (int k = 0; k < 8; ++k) {
        ulonglong2 v = src[k];
        f[2 * k] = v.x; f[2 * k + 1] = v.y;
    }

    // local pass from zero state: z' = m11 z + m12 x + c1 f ; x' = m21 z + m22 x + c2 f
    ull z = 0, x = 0;
#pragma unroll
    for (int i = 0; i < 16; ++i) {
        ull nz = fma2(M11, z, fma2(M12, x, mul2(C1, f[i])));
        ull nx = fma2(M21, z, fma2(M22, x, mul2(C2, f[i])));
        z = nz; x = nx;
    }

    // M^16 by 4 squarings (scalar)
    float q00 = m11, q01 = m12, q10 = m21, q11 = m22;
#pragma unroll
    for (int k = 0; k < 4; ++k) {
        float n00 = q00*q00 + q01*q10, n01 = q00*q01 + q01*q11;
        float n10 = q10*q00 + q11*q10, n11 = q10*q01 + q11*q11;
        q00 = n00; q01 = n01; q10 = n10; q11 = n11;
    }

    // Hillis-Steele inclusive scan over 512 thread-segments
    __shared__ ulonglong2 sv[512];
    ull vz = z, vx = x;
    int off = 1;
#pragma unroll
    for (int st = 0; st < 9; ++st) {
        sv[t] = make_ulonglong2(vz, vx);
        __syncthreads();
        if (t >= off) {
            ulonglong2 w = sv[t - off];
            ull Q00 = dup2(q00), Q01 = dup2(q01), Q10 = dup2(q10), Q11 = dup2(q11);
            ull nvz = fma2(Q00, w.x, fma2(Q01, w.y, vz));
            ull nvx = fma2(Q10, w.x, fma2(Q11, w.y, vx));
            vz = nvz; vx = nvx;
        }
        __syncthreads();
        float n00 = q00*q00 + q01*q10, n01 = q00*q01 + q01*q11;
        float n10 = q10*q00 + q11*q10, n11 = q10*q01 + q11*q11;
        q00 = n00; q01 = n01; q10 = n10; q11 = n11;
        off <<= 1;
    }
    sv[t] = make_ulonglong2(vz, vx);
    __syncthreads();
    ull z0 = 0, x0 = 0;
    if (t > 0) { ulonglong2 w = sv[t - 1]; z0 = w.x; x0 = w.y; }

    // replay with correct start state; emit x (position) component
    z = z0; x = x0;
#pragma unroll
    for (int i = 0; i < 16; ++i) {
        ull nz = fma2(M11, z, fma2(M12, x, mul2(C1, f[i])));
        ull nx = fma2(M21, z, fma2(M22, x, mul2(C2, f[i])));
        z = nz; x = nx;
        f[i] = x;
    }
    ulonglong2* dst = (ulonglong2*)(g_ys) + chain * (Ln / 2) + t * 8;
#pragma unroll
    for (int k = 0; k < 8; ++k) dst[k] = make_ulonglong2(f[2 * k], f[2 * k + 1]);
}

// ---------- Kernel 3: y = ys_re @ Cr^T - ys_im @ Ci^T + D*u ----------
#define YPW 132   // sy pitch floats: [64 p][2l pairs + pad]  (66 ull)
#define CPW 132   // sC pitch floats: [64 h][2p pairs + pad]  (66 ull), holds (Cr, -Ci)

__global__ __launch_bounds__(256) void k_gemmD(const float* __restrict__ u,
                                               const float* __restrict__ Cr,
                                               const float* __restrict__ Ci,
                                               const float* __restrict__ Dv,
                                               float* __restrict__ out) {
    extern __shared__ float sm[];
    float* sy = sm;               // [64][YPW]
    float* sC = sm + Pn * YPW;    // [64][CPW]
    const int b = blockIdx.y, lt = blockIdx.x, hh = blockIdx.z;   // Ltile=64, Htile=64
    const int tid = threadIdx.x;

    // stage ys tile: 64 p x 64 l pairs
    for (int e = tid; e < Pn * 32; e += 256) {
        int p = e >> 5, g = e & 31;   // g: 2-l group
        const ulonglong2* yg = (const ulonglong2*)(g_ys) +
            ((size_t)(b * Pn + p) * Ln + (size_t)lt * 64) / 2 + g;
        ulonglong2 v = *yg;
        *(ulonglong2*)&sy[p * YPW + 4 * g] = v;
    }
    // stage C tile: 64 h x 64 p pairs (Cr, -Ci)
    for (int e = tid; e < 64 * Pn; e += 256) {
        int h = e >> 6, pp = e & 63;
        int gidx = (hh * 64 + h) * Pn + pp;
        sC[h * CPW + 2 * pp]     = Cr[gidx];
        sC[h * CPW + 2 * pp + 1] = -Ci[gidx];
    }
    __syncthreads();

    const int tx = tid & 15, ty = tid >> 4;    // 16 x 16
    const int lA = 2 * tx, lB = 32 + 2 * tx;   // 2 l each group
    const int hl = 4 * ty;                     // local h base

    ull accA[2][4], accB[2][4];
#pragma unroll
    for (int i = 0; i < 2; ++i)
#pragma unroll
        for (int j = 0; j < 4; ++j) { accA[i][j] = 0; accB[i][j] = 0; }

#pragma unroll 2
    for (int p = 0; p < Pn; p += 2) {
        ulonglong2 yA0 = *(const ulonglong2*)&sy[p * YPW + 2 * lA];
        ulonglong2 yA1 = *(const ulonglong2*)&sy[(p + 1) * YPW + 2 * lA];
        ulonglong2 yB0 = *(const ulonglong2*)&sy[p * YPW + 2 * lB];
        ulonglong2 yB1 = *(const ulonglong2*)&sy[(p + 1) * YPW + 2 * lB];
#pragma unroll
        for (int j = 0; j < 4; ++j) {
            ulonglong2 cj = *(const ulonglong2*)&sC[(hl + j) * CPW + 2 * p];
            accA[0][j] = fma2(yA0.x, cj.x, accA[0][j]);
            accA[0][j] = fma2(yA1.x, cj.y, accA[0][j]);
            accA[1][j] = fma2(yA0.y, cj.x, accA[1][j]);
            accA[1][j] = fma2(yA1.y, cj.y, accA[1][j]);
            accB[0][j] = fma2(yB0.x, cj.x, accB[0][j]);
            accB[0][j] = fma2(yB1.x, cj.y, accB[0][j]);
            accB[1][j] = fma2(yB0.y, cj.x, accB[1][j]);
            accB[1][j] = fma2(yB1.y, cj.y, accB[1][j]);
        }
    }

    const int h0 = hh * 64 + hl;
    float4 dv4 = *(const float4*)&Dv[h0];
    float dv[4] = {dv4.x, dv4.y, dv4.z, dv4.w};

#pragma unroll
    for (int g = 0; g < 4; ++g) {
        int l = (g < 2) ? (lA + g) : (lB + (g - 2));
        ull* arow = (g < 2) ? accA[g] : accB[g - 2];
        size_t row = ((size_t)b * Ln + (size_t)lt * 64 + l) * Hn + h0;
        float4 uu = *(const float4*)&u[row];
        float uv[4] = {uu.x, uu.y, uu.z, uu.w};
        float y[4];
#pragma unroll
        for (int j = 0; j < 4; ++j) {
            float lo, hi; unpack2(arow[j], lo, hi);
            y[j] = lo + hi + dv[j] * uv[j];
        }
        *(float4*)&out[row] = make_float4(y[0], y[1], y[2], y[3]);
    }
}

// ---------- launch ----------
extern "C" void kernel_launch(void* const* d_in, const int* in_sizes, int n_in,
                              void* d_out, int out_size) {
    const float* u     = (const float*)d_in[0];
    const float* A_d   = (const float*)d_in[1];
    const float* Br    = (const float*)d_in[2];
    const float* Bi    = (const float*)d_in[3];
    const float* Cr    = (const float*)d_in[4];
    const float* Ci    = (const float*)d_in[5];
    const float* Dv    = (const float*)d_in[6];
    const float* steps = (const float*)d_in[7];
    float* out = (float*)d_out;

    const int SMB = (128 * UP + Pn * BPW) * 4;   // 101,376 B -> 2 blocks/SM
    const int SMD = (Pn * YPW + 64 * CPW) * 4;   //  67,584 B -> 3 blocks/SM
    cudaFuncSetAttribute(k_gemmB, cudaFuncAttributeMaxDynamicSharedMemorySize, SMB);
    cudaFuncSetAttribute(k_gemmD, cudaFuncAttributeMaxDynamicSharedMemorySize, SMD);

    k_gemmB<<<dim3(Ln / 64, Bn), 256, SMB>>>(u, Br, Bi);
    k_recur<<<dim3(Pn, Bn), 512>>>(A_d, steps);
    k_gemmD<<<dim3(Ln / 64, Bn, 2), 256, SMD>>>(u, Cr, Ci, Dv, out);
}